// round 10
// baseline (speedup 1.0000x reference)
#include <cuda_runtime.h>

#define BB 64
#define NN 65536
#define RADIUS 0.2f

// Scratch (__device__ globals per allocation-free rule)
__device__ float4   g_xyz4[(size_t)BB * NN];        // packed xyz (w unused), 64 MB
__device__ float    g_pval[3][BB * 64];             // argmax partials per FPS step
__device__ int      g_pidx[3][BB * 64];
__device__ unsigned g_bm[BB * (NN / 32)];           // keep bitmask, 512 KB
__device__ int      g_cnt[BB * 64];                 // per-chunk keep counts (64 chunks)
__device__ int      g_numvalid[BB];

// ---------------------------------------------------------------------------
// Argmax helpers: larger value wins, tie -> smaller index (jnp.argmax semantics)
// ---------------------------------------------------------------------------
__device__ __forceinline__ void warp_argmax(float& v, int& i) {
    #pragma unroll
    for (int off = 16; off; off >>= 1) {
        float ov = __shfl_down_sync(0xffffffffu, v, off);
        int   oi = __shfl_down_sync(0xffffffffu, i, off);
        if (ov > v || (ov == v && oi < i)) { v = ov; i = oi; }
    }
}

// 256-thread (8-warp) block argmax; result valid in thread 0.
__device__ __forceinline__ void block_argmax256(float& v, int& i, int tid,
                                                float* s_val, int* s_idx) {
    warp_argmax(v, i);
    if ((tid & 31) == 0) { s_val[tid >> 5] = v; s_idx[tid >> 5] = i; }
    __syncthreads();
    if (tid < 32) {
        v = (tid < 8) ? s_val[tid] : -2.0f;
        i = (tid < 8) ? s_idx[tid] : NN;
        warp_argmax(v, i);
    }
}

// Reduce 64 partials of set j -> argmax (lane 0 of calling warp holds result).
__device__ __forceinline__ void reduce_partials(int j, int b, int lane,
                                                float& v, int& i) {
    v = g_pval[j][b * 64 + lane];
    i = g_pidx[j][b * 64 + lane];
    float v2 = g_pval[j][b * 64 + 32 + lane];
    int   i2 = g_pidx[j][b * 64 + 32 + lane];
    if (v2 > v || (v2 == v && i2 < i)) { v = v2; i = i2; }
    warp_argmax(v, i);
}

// Recover centers 1..S-1 from partial sets (center 0 = point 0 of batch).
template <int S>
__device__ __forceinline__ void recover_centers(const float* __restrict__ pts,
                                                int b, int tid, float3* sc) {
    const size_t bb = (size_t)b * NN;
    if (tid == 0) {
        const float* q = pts + bb * 6;
        sc[0] = make_float3(q[0], q[1], q[2]);
    }
    if (tid < 32) {
        #pragma unroll
        for (int j = 0; j < S - 1; j++) {
            float v; int i;
            reduce_partials(j, b, tid, v, i);
            if (tid == 0) {
                float4 c = g_xyz4[bb + i];
                sc[j + 1] = make_float3(c.x, c.y, c.z);
            }
        }
    }
    __syncthreads();
}

// ---------------------------------------------------------------------------
// K1: read raw pts, write packed float4 xyz, dist-to-center0 argmax partials.
// grid (64, BB) x 256; 1024 pts/block. Loads batched up front.
// ---------------------------------------------------------------------------
__global__ void __launch_bounds__(256) sweep1_pack_kernel(const float* __restrict__ pts) {
    const int b = blockIdx.y, chunk = blockIdx.x, tid = threadIdx.x;
    const float* __restrict__ base = pts + (size_t)b * NN * 6;
    const float cx = __ldg(base), cy = __ldg(base + 1), cz = __ldg(base + 2);
    const size_t bb = (size_t)b * NN;

    __shared__ float s_val[8];
    __shared__ int   s_idx[8];

    const int p0 = chunk * 1024;
    float qx[4], qy[4], qz[4];
    #pragma unroll
    for (int k = 0; k < 4; k++) {
        const float* q = base + (size_t)(p0 + k * 256 + tid) * 6;
        float2 xy = *(const float2*)q;
        qx[k] = xy.x; qy[k] = xy.y; qz[k] = q[2];
    }
    float best = -1.0f;
    int bidx = NN;
    #pragma unroll
    for (int k = 0; k < 4; k++) {
        int p = p0 + k * 256 + tid;
        g_xyz4[bb + p] = make_float4(qx[k], qy[k], qz[k], 0.0f);
        float dx = qx[k] - cx, dy = qy[k] - cy, dz = qz[k] - cz;
        float d = dx * dx + dy * dy + dz * dz;
        if (d > best || (d == best && p < bidx)) { best = d; bidx = p; }
    }
    block_argmax256(best, bidx, tid, s_val, s_idx);
    if (tid == 0) {
        g_pval[0][b * 64 + chunk] = best;
        g_pidx[0][b * 64 + chunk] = bidx;
    }
}

// ---------------------------------------------------------------------------
// K2/K3: FPS sweep with S known centers (S=2,3). float4 loads, batch 4.
// grid (64, BB) x 256; 1024 pts/block.
// ---------------------------------------------------------------------------
template <int S>
__global__ void __launch_bounds__(256) sweep_kernel(const float* __restrict__ pts) {
    const int b = blockIdx.y, chunk = blockIdx.x, tid = threadIdx.x;
    const size_t bb = (size_t)b * NN;
    __shared__ float3 sc[S];
    __shared__ float s_val[8];
    __shared__ int   s_idx[8];

    recover_centers<S>(pts, b, tid, sc);

    const int p0 = chunk * 1024;
    float4 q[4];
    #pragma unroll
    for (int k = 0; k < 4; k++) q[k] = g_xyz4[bb + p0 + k * 256 + tid];

    float best = -1.0f;
    int bidx = NN;
    #pragma unroll
    for (int k = 0; k < 4; k++) {
        int p = p0 + k * 256 + tid;
        float m = 1e10f;
        #pragma unroll
        for (int t = 0; t < S; t++) {
            float dx = q[k].x - sc[t].x, dy = q[k].y - sc[t].y, dz = q[k].z - sc[t].z;
            float d = dx * dx + dy * dy + dz * dz;
            m = fminf(m, d);
        }
        if (m > best || (m == best && p < bidx)) { best = m; bidx = p; }
    }
    block_argmax256(best, bidx, tid, s_val, s_idx);
    if (tid == 0) {
        g_pval[S - 1][b * 64 + chunk] = best;
        g_pidx[S - 1][b * 64 + chunk] = bidx;
    }
}

// ---------------------------------------------------------------------------
// K4: keep test against 4 centers -> bitmask + per-chunk counts.
// grid (64, BB) x 256; 1024 pts/block, batch 4 float4 loads.
// ---------------------------------------------------------------------------
__global__ void __launch_bounds__(256) keep_kernel(const float* __restrict__ pts) {
    const int b = blockIdx.y, chunk = blockIdx.x, tid = threadIdx.x;
    const size_t bb = (size_t)b * NN;
    __shared__ float3 sc[4];
    __shared__ int s_c[8];

    recover_centers<4>(pts, b, tid, sc);

    const int lane = tid & 31, warp = tid >> 5;
    const int p0 = chunk * 1024;

    float4 q[4];
    #pragma unroll
    for (int k = 0; k < 4; k++) q[k] = g_xyz4[bb + p0 + k * 256 + tid];

    int cnt = 0;
    #pragma unroll
    for (int k = 0; k < 4; k++) {
        int p = p0 + k * 256 + tid;
        float m = 1e10f;
        #pragma unroll
        for (int t = 0; t < 4; t++) {
            float dx = q[k].x - sc[t].x, dy = q[k].y - sc[t].y, dz = q[k].z - sc[t].z;
            float d = dx * dx + dy * dy + dz * dz;
            m = fminf(m, d);
        }
        bool keep = (sqrtf(m) >= RADIUS);   // == (norm >= 0.2), sqrt monotone
        unsigned w = __ballot_sync(0xffffffffu, keep);
        if (lane == 0) g_bm[b * (NN / 32) + (p >> 5)] = w;
        cnt += keep;
    }
    #pragma unroll
    for (int off = 16; off; off >>= 1) cnt += __shfl_down_sync(0xffffffffu, cnt, off);
    if (lane == 0) s_c[warp] = cnt;
    __syncthreads();
    if (tid == 0) {
        int tot = 0;
        #pragma unroll
        for (int i = 0; i < 8; i++) tot += s_c[i];
        g_cnt[b * 64 + chunk] = tot;
    }
}

// ---------------------------------------------------------------------------
// K5: scatter kept points directly to out[rank]. grid (64, BB) x 256.
// 1024 pts/block, 32 bitmask words. Unconditional batched loads.
// ---------------------------------------------------------------------------
__global__ void __launch_bounds__(256) scatter_kernel(const float* __restrict__ pts,
                                                      float* __restrict__ out) {
    const int b = blockIdx.y, chunk = blockIdx.x, tid = threadIdx.x;
    __shared__ unsigned s_w[32];
    __shared__ int s_wpref[32];
    __shared__ int s_cwarp[2];       // warp totals for 64-chunk scan
    __shared__ int s_chunk_off;

    // warps 0-1: exclusive scan of the batch's 64 chunk counts
    if (tid < 64) {
        int lane = tid & 31;
        int v = g_cnt[b * 64 + tid];
        int inc = v;
        #pragma unroll
        for (int off = 1; off < 32; off <<= 1) {
            int n = __shfl_up_sync(0xffffffffu, inc, off);
            if (lane >= off) inc += n;
        }
        if (lane == 31) s_cwarp[tid >> 5] = inc;
        // stash exclusive partial in shared via s_wpref reuse? use separate path:
        if (tid == chunk) s_chunk_off = inc - v;          // valid if chunk < 32
        __syncthreads();
        if (tid >= 32 && tid == chunk) s_chunk_off += s_cwarp[0];
        if (chunk >= 32 && tid == chunk - 32) { /* no-op placeholder */ }
        if (tid == 63 && chunk == 0) g_numvalid[b] = s_cwarp[0] + s_cwarp[1];
    } else {
        __syncthreads();
    }
    // load this chunk's 32 bitmask words (warp 4)
    if (tid >= 128 && tid < 160) s_w[tid - 128] = g_bm[b * (NN / 32) + chunk * 32 + (tid - 128)];
    __syncthreads();

    // exclusive word-prefix over 32 popcounts (warp 0)
    if (tid < 32) {
        int pc = __popc(s_w[tid]);
        int inc = pc;
        #pragma unroll
        for (int off = 1; off < 32; off <<= 1) {
            int n = __shfl_up_sync(0xffffffffu, inc, off);
            if (tid >= off) inc += n;
        }
        s_wpref[tid] = inc - pc;
    }
    __syncthreads();

    const float* __restrict__ base = pts + (size_t)b * NN * 6;
    float* __restrict__ obase = out + (size_t)b * NN * 6;
    const int p0 = chunk * 1024;

    // batched unconditional loads of 4 rows (12 independent float2 LDGs)
    float2 r[4][3];
    #pragma unroll
    for (int k = 0; k < 4; k++) {
        const float2* s = (const float2*)(base + (size_t)(p0 + k * 256 + tid) * 6);
        r[k][0] = s[0]; r[k][1] = s[1]; r[k][2] = s[2];
    }
    #pragma unroll
    for (int k = 0; k < 4; k++) {
        int pl = k * 256 + tid;                 // local point 0..1023
        unsigned word = s_w[pl >> 5];
        int bit = pl & 31;
        if ((word >> bit) & 1u) {
            int rank = s_chunk_off + s_wpref[pl >> 5] + __popc(word & ((1u << bit) - 1u));
            float2* o = (float2*)(obase + (size_t)rank * 6);
            o[0] = r[k][0]; o[1] = r[k][1]; o[2] = r[k][2];
        }
    }
}

// ---------------------------------------------------------------------------
// K6: tail fill: rows j >= nv copy from out[j % nv]; nv==0 -> zeros.
// Source rows were written by K5 (previous kernel) — no hazard.
// ---------------------------------------------------------------------------
__global__ void __launch_bounds__(256) tail_kernel(float* __restrict__ out) {
    int i = blockIdx.x * blockDim.x + threadIdx.x;
    if (i >= BB * NN) return;
    int b = i >> 16;
    int j = i & (NN - 1);
    int nv = g_numvalid[b];
    float* __restrict__ obase = out + (size_t)b * NN * 6;
    if (nv == 0) {
        float2 z = make_float2(0.f, 0.f);
        float2* o = (float2*)(obase + (size_t)j * 6);
        o[0] = z; o[1] = z; o[2] = z;
        return;
    }
    if (j < nv) return;
    int k = j % nv;
    const float2* s = (const float2*)(obase + (size_t)k * 6);
    float2 a0 = s[0], a1 = s[1], a2 = s[2];
    float2* o = (float2*)(obase + (size_t)j * 6);
    o[0] = a0; o[1] = a1; o[2] = a2;
}

extern "C" void kernel_launch(void* const* d_in, const int* in_sizes, int n_in,
                              void* d_out, int out_size) {
    const float* pts = (const float*)d_in[0];
    float* out = (float*)d_out;
    (void)in_sizes; (void)n_in; (void)out_size;

    sweep1_pack_kernel<<<dim3(64, BB), 256>>>(pts);
    sweep_kernel<2><<<dim3(64, BB), 256>>>(pts);
    sweep_kernel<3><<<dim3(64, BB), 256>>>(pts);
    keep_kernel<<<dim3(64, BB), 256>>>(pts);
    scatter_kernel<<<dim3(64, BB), 256>>>(pts, out);
    tail_kernel<<<(BB * NN + 255) / 256, 256>>>(out);
}